// round 7
// baseline (speedup 1.0000x reference)
#include <cuda_runtime.h>
#include <math.h>

// ---------------------------------------------------------------------------
// GRAPEIso: conv3x3(3->1024) + pixel_shuffle(4) + pixel_unshuffle(2) + head
// algebraically folded into a 96-output 3x3 conv, then Gaussian splatting
// with exclusive shared-memory image tiles (no global atomics).
// Fixed shapes: B=4, inp 3x128x128, scale=2, grid 256x256 gaussians/batch,
// image 4x3x256x256 fp32 output.
// ---------------------------------------------------------------------------

#define BATCH   4
#define INH     128
#define INW     128
#define GH      256
#define GW      256
#define IMH     256
#define IMW     256
#define NGAUSS  (GH * GW)

// Raster tiling: 16x16 image tile per CTA -> 1024 CTAs. 4x4 footprint,
// 22x22 gather halo.
#define TW      16
#define TH      16
#define RSX     22
#define RSY     22

__device__ __forceinline__ float tanh_approx(float x) {
    float r;
    asm("tanh.approx.f32 %0, %1;" : "=f"(r) : "f"(x));
    return r;
}

// Scratch (allocation-free contract: __device__ globals)
__device__ float  g_weff[4 * 27 * 24];          // [uv][t][o], o contiguous
__device__ float  g_beff[4 * 24];               // [uv][o]
__device__ float2 g_center[BATCH * NGAUSS];     // (cx, cy)
__device__ float4 g_color [BATCH * NGAUSS];     // (r, g, b, pad)

// ---------------------------------------------------------------------------
// Kernel 0: weight fold, coalesced layout. One CTA per (uv, o): 96 CTAs x
// 128 threads (4 warps). LANE = t (0..26; lane 27 = bias term), so each
// warp-LDG of w_enc reads 27 consecutive floats of ONE row (1-2 cache
// lines vs 32 in the lane=channel layout: ~30x less L2 traffic, which was
// the measured fold bound). w_head factor is warp-uniform (broadcast load).
// Each warp reduces 64 of the 256 channels; smem combine across warps.
// ---------------------------------------------------------------------------
__global__ void __launch_bounds__(128) fold_kernel(
    const float* __restrict__ w_enc,   // (1024, 3, 3, 3) -> [C*27 + t]
    const float* __restrict__ b_enc,   // (1024,)
    const float* __restrict__ w_head,  // (24, 256)
    const float* __restrict__ b_head)  // (24,)
{
    __shared__ float red[4][28];

    int uv = blockIdx.x / 24;          // grid 96
    int o  = blockIdx.x - uv * 24;
    int u = uv >> 1, v = uv & 1;

    int warp = threadIdx.x >> 5;
    int lane = threadIdx.x & 31;

    float acc = 0.f;
    if (lane < 28) {
        #pragma unroll 8
        for (int i = 0; i < 64; i++) {
            int ch = warp * 64 + i;
            int c = ch >> 2, a = (ch >> 1) & 1, e = ch & 1;
            int C = c * 16 + (2 * u + a) * 4 + (2 * v + e);
            float wh = __ldg(w_head + o * 256 + ch);           // warp-uniform
            float x  = (lane < 27) ? __ldg(w_enc + C * 27 + lane)
                                   : __ldg(b_enc + C);
            acc = fmaf(wh, x, acc);
        }
        red[warp][lane] = acc;
    }
    __syncthreads();

    if (threadIdx.x < 28) {
        int t = threadIdx.x;
        float s = red[0][t] + red[1][t] + red[2][t] + red[3][t];
        if (t < 27) g_weff[uv * 648 + t * 24 + o] = s;
        else        g_beff[uv * 24 + o] = s + b_head[o];
    }
}

// ---------------------------------------------------------------------------
// Kernel 1: predict (exact R4 version - the 41.5us config; predict variants
// R5/R6 proved neutral-to-negative, so it is frozen while fold/raster move).
// 1024 CTAs x 64 threads; scalar FFMA; per-thread patch from global.
// ---------------------------------------------------------------------------
__global__ void __launch_bounds__(64) predict_kernel(const float* __restrict__ inp)
{
    __shared__ __align__(16) float sW[4 * 648];      // [uv][t][o]
    __shared__ float sB[4 * 24];

    for (int i = threadIdx.x; i < 4 * 648; i += 64) sW[i] = g_weff[i];
    for (int i = threadIdx.x; i < 96; i += 64) sB[i] = g_beff[i];
    __syncthreads();

    int idx = blockIdx.x * 64 + threadIdx.x;    // 0..65535
    int b   = idx >> 14;
    int rem = idx & 16383;
    int i   = rem >> 7;
    int j   = rem & 127;

    // Load 3x3x3 input patch with zero padding (SAME conv)
    float patch[27];
    const float* ib = inp + (size_t)b * 3 * INH * INW;
    #pragma unroll
    for (int ic = 0; ic < 3; ic++) {
        #pragma unroll
        for (int ky = 0; ky < 3; ky++) {
            int y = i + ky - 1;
            #pragma unroll
            for (int kx = 0; kx < 3; kx++) {
                int x = j + kx - 1;
                float vv = 0.f;
                if ((unsigned)y < INH && (unsigned)x < INW)
                    vv = __ldg(ib + ic * INH * INW + y * INW + x);
                patch[ic * 9 + ky * 3 + kx] = vv;
            }
        }
    }

    #pragma unroll
    for (int uv = 0; uv < 4; uv++) {
        float acc[24];
        #pragma unroll
        for (int o = 0; o < 24; o++) acc[o] = sB[uv * 24 + o];

        const float4* wrow = (const float4*)(sW + uv * 648);
        #pragma unroll
        for (int t = 0; t < 27; t++) {
            float xv = patch[t];
            #pragma unroll
            for (int q = 0; q < 6; q++) {
                float4 wv = wrow[t * 6 + q];
                acc[q * 4 + 0] = fmaf(wv.x, xv, acc[q * 4 + 0]);
                acc[q * 4 + 1] = fmaf(wv.y, xv, acc[q * 4 + 1]);
                acc[q * 4 + 2] = fmaf(wv.z, xv, acc[q * 4 + 2]);
                acc[q * 4 + 3] = fmaf(wv.w, xv, acc[q * 4 + 3]);
            }
        }

        float lg0 = acc[5], lg1 = acc[11], lg2 = acc[17], lg3 = acc[23];
        float m = fmaxf(fmaxf(lg0, lg1), fmaxf(lg2, lg3));
        float w0 = __expf(lg0 - m), w1 = __expf(lg1 - m);
        float w2 = __expf(lg2 - m), w3 = __expf(lg3 - m);
        float inv = 1.f / (w0 + w1 + w2 + w3);

        float r = 0.f, g = 0.f, bl = 0.f, ox = 0.f, oy = 0.f;
        #pragma unroll
        for (int k = 0; k < 4; k++) {
            float wk = ((k == 0) ? w0 : (k == 1) ? w1 : (k == 2) ? w2 : w3) * inv;
            r  = fmaf(acc[k * 6 + 0], wk, r);
            g  = fmaf(acc[k * 6 + 1], wk, g);
            bl = fmaf(acc[k * 6 + 2], wk, bl);
            ox = fmaf(tanh_approx(acc[k * 6 + 3]), wk, ox);
            oy = fmaf(tanh_approx(acc[k * 6 + 4]), wk, oy);
        }

        int u = uv >> 1, v = uv & 1;
        int gy = 2 * i + u, gx = 2 * j + v;
        float cx = (float)gx + 2.f * ox - 1.f;
        float cy = (float)gy + 2.f * oy - 1.f;

        int gidx = b * NGAUSS + gy * GW + gx;
        g_center[gidx] = make_float2(cx, cy);
        g_color[gidx]  = make_float4(r, g, bl, 0.f);
    }
}

// ---------------------------------------------------------------------------
// Kernel 2: rasterize. One CTA per 16x16 tile per batch (1024 CTAs).
// Effective footprint 4x4 (alpha cutoff kills |d|>=2); gather halo 22x22;
// stride-5 lane permutation spreads footprints.
// CHANGE vs R4: accumulator layout acc[3*p + ch] instead of [ch][p].
// The old plane stride (256 words = 0 mod 32 banks) made each splat's three
// channel atomics a guaranteed 3-way same-bank conflict; interleaving puts
// them in 3 consecutive banks. Final-store reads at stride 3 (coprime to
// 32) stay conflict-free and the global stores stay coalesced.
// ---------------------------------------------------------------------------
__global__ void __launch_bounds__(256) raster_kernel(float* __restrict__ out)
{
    __shared__ float acc[3 * TH * TW];  // interleaved [p][ch]

    int tx0 = (blockIdx.x & 15) * TW;
    int ty0 = (blockIdx.x >> 4) * TH;
    int b   = blockIdx.y;

    for (int p = threadIdx.x; p < 3 * TH * TW; p += 256) acc[p] = 0.f;
    __syncthreads();

    const float2* ctr = g_center + b * NGAUSS;
    const float4* col = g_color  + b * NGAUSS;

    for (int idx = threadIdx.x; idx < RSX * RSY; idx += 256) {
        int ry = idx / RSX;
        int j  = idx - ry * RSX;
        int rx = (j * 5) % RSX;
        int gy = ty0 - 2 + ry;
        int gx = tx0 - 2 + rx;
        if ((unsigned)gy >= GH || (unsigned)gx >= GW) continue;

        int gi = gy * GW + gx;
        float2 c = ctr[gi];

        float ixf = floorf(c.x);
        float iyf = floorf(c.y);

        int txl = (int)ixf - 1 - tx0;
        int tyl = (int)iyf - 1 - ty0;
        if (txl >= TW || txl <= -4 || tyl >= TH || tyl <= -4) continue;

        float4 rgbv = col[gi];

        float ex[4], ey[4];
        #pragma unroll
        for (int o = 0; o < 4; o++) {
            float dx = ixf + (float)(o - 1) - c.x;
            float dy = iyf + (float)(o - 1) - c.y;
            ex[o] = __expf(-2.f * dx * dx);
            ey[o] = __expf(-2.f * dy * dy);
        }

        #pragma unroll
        for (int oy = 0; oy < 4; oy++) {
            int ty = tyl + oy;
            if ((unsigned)ty >= TH) continue;
            float eyv = ey[oy];
            #pragma unroll
            for (int ox = 0; ox < 4; ox++) {
                int tx = txl + ox;
                if ((unsigned)tx >= TW) continue;
                float a = fminf(eyv * ex[ox], 0.999f);
                if (a > (1.0f / 255.0f)) {
                    int p3 = (ty * TW + tx) * 3;
                    atomicAdd(&acc[p3 + 0], a * rgbv.x);
                    atomicAdd(&acc[p3 + 1], a * rgbv.y);
                    atomicAdd(&acc[p3 + 2], a * rgbv.z);
                }
            }
        }
    }
    __syncthreads();

    float* ob = out + (size_t)b * 3 * IMH * IMW;
    for (int p = threadIdx.x; p < TH * TW; p += 256) {
        int ty = p >> 4;
        int tx = p & 15;
        int o  = (ty0 + ty) * IMW + (tx0 + tx);
        #pragma unroll
        for (int ch = 0; ch < 3; ch++) {
            float vv = acc[p * 3 + ch];
            ob[ch * IMH * IMW + o] = fminf(fmaxf(vv, 0.f), 1.f);
        }
    }
}

// ---------------------------------------------------------------------------
// Launch: fold -> predict -> raster, all graph-capturable, no allocs/syncs.
// Inputs (metadata order): inp, w_enc, b_enc, w_head, b_head, scale(unused)
// ---------------------------------------------------------------------------
extern "C" void kernel_launch(void* const* d_in, const int* in_sizes, int n_in,
                              void* d_out, int out_size)
{
    const float* inp    = (const float*)d_in[0];
    const float* w_enc  = (const float*)d_in[1];
    const float* b_enc  = (const float*)d_in[2];
    const float* w_head = (const float*)d_in[3];
    const float* b_head = (const float*)d_in[4];
    float* out = (float*)d_out;

    fold_kernel<<<96, 128>>>(w_enc, b_enc, w_head, b_head);
    predict_kernel<<<1024, 64>>>(inp);

    dim3 g(256, BATCH);
    raster_kernel<<<g, 256>>>(out);
}

// round 8
// speedup vs baseline: 1.0079x; 1.0079x over previous
#include <cuda_runtime.h>
#include <math.h>

// ---------------------------------------------------------------------------
// GRAPEIso: conv3x3(3->1024) + pixel_shuffle(4) + pixel_unshuffle(2) + head
// algebraically folded into a 96-output 3x3 conv, then Gaussian splatting
// with exclusive shared-memory image tiles (no global atomics).
// Fixed shapes: B=4, inp 3x128x128, scale=2, grid 256x256 gaussians/batch,
// image 4x3x256x256 fp32 output.
// ---------------------------------------------------------------------------

#define BATCH   4
#define INH     128
#define INW     128
#define GH      256
#define GW      256
#define IMH     256
#define IMW     256
#define NGAUSS  (GH * GW)

// Raster tiling: 16x16 image tile per CTA -> 1024 CTAs. 4x4 footprint,
// 22x22 gather halo.
#define TW      16
#define TH      16
#define RSX     22
#define RSY     22

__device__ __forceinline__ float tanh_approx(float x) {
    float r;
    asm("tanh.approx.f32 %0, %1;" : "=f"(r) : "f"(x));
    return r;
}

// Scratch (allocation-free contract: __device__ globals)
__device__ float  g_weff[4 * 27 * 24];          // [uv][t][o], o contiguous
__device__ float  g_beff[4 * 24];               // [uv][o]
__device__ float2 g_center[BATCH * NGAUSS];     // (cx, cy)
__device__ float4 g_color [BATCH * NGAUSS];     // (r, g, b, pad)

// ---------------------------------------------------------------------------
// Kernel 0: weight fold, coalesced layout. One CTA per (uv, o): 96 CTAs x
// 128 threads (4 warps). LANE = t (0..26; lane 27 = bias term), so each
// warp-LDG of w_enc reads 27 consecutive floats of ONE row (1-2 cache
// lines vs 32 in the lane=channel layout: ~30x less L2 traffic, which was
// the measured fold bound). w_head factor is warp-uniform (broadcast load).
// Each warp reduces 64 of the 256 channels; smem combine across warps.
// ---------------------------------------------------------------------------
__global__ void __launch_bounds__(128) fold_kernel(
    const float* __restrict__ w_enc,   // (1024, 3, 3, 3) -> [C*27 + t]
    const float* __restrict__ b_enc,   // (1024,)
    const float* __restrict__ w_head,  // (24, 256)
    const float* __restrict__ b_head)  // (24,)
{
    __shared__ float red[4][28];

    int uv = blockIdx.x / 24;          // grid 96
    int o  = blockIdx.x - uv * 24;
    int u = uv >> 1, v = uv & 1;

    int warp = threadIdx.x >> 5;
    int lane = threadIdx.x & 31;

    float acc = 0.f;
    if (lane < 28) {
        #pragma unroll 8
        for (int i = 0; i < 64; i++) {
            int ch = warp * 64 + i;
            int c = ch >> 2, a = (ch >> 1) & 1, e = ch & 1;
            int C = c * 16 + (2 * u + a) * 4 + (2 * v + e);
            float wh = __ldg(w_head + o * 256 + ch);           // warp-uniform
            float x  = (lane < 27) ? __ldg(w_enc + C * 27 + lane)
                                   : __ldg(b_enc + C);
            acc = fmaf(wh, x, acc);
        }
        red[warp][lane] = acc;
    }
    __syncthreads();

    if (threadIdx.x < 28) {
        int t = threadIdx.x;
        float s = red[0][t] + red[1][t] + red[2][t] + red[3][t];
        if (t < 27) g_weff[uv * 648 + t * 24 + o] = s;
        else        g_beff[uv * 24 + o] = s + b_head[o];
    }
}

// ---------------------------------------------------------------------------
// Kernel 1: predict (exact R4 version - the 41.5us config; predict variants
// R5/R6 proved neutral-to-negative, so it is frozen while fold/raster move).
// 1024 CTAs x 64 threads; scalar FFMA; per-thread patch from global.
// ---------------------------------------------------------------------------
__global__ void __launch_bounds__(64) predict_kernel(const float* __restrict__ inp)
{
    __shared__ __align__(16) float sW[4 * 648];      // [uv][t][o]
    __shared__ float sB[4 * 24];

    for (int i = threadIdx.x; i < 4 * 648; i += 64) sW[i] = g_weff[i];
    for (int i = threadIdx.x; i < 96; i += 64) sB[i] = g_beff[i];
    __syncthreads();

    int idx = blockIdx.x * 64 + threadIdx.x;    // 0..65535
    int b   = idx >> 14;
    int rem = idx & 16383;
    int i   = rem >> 7;
    int j   = rem & 127;

    // Load 3x3x3 input patch with zero padding (SAME conv)
    float patch[27];
    const float* ib = inp + (size_t)b * 3 * INH * INW;
    #pragma unroll
    for (int ic = 0; ic < 3; ic++) {
        #pragma unroll
        for (int ky = 0; ky < 3; ky++) {
            int y = i + ky - 1;
            #pragma unroll
            for (int kx = 0; kx < 3; kx++) {
                int x = j + kx - 1;
                float vv = 0.f;
                if ((unsigned)y < INH && (unsigned)x < INW)
                    vv = __ldg(ib + ic * INH * INW + y * INW + x);
                patch[ic * 9 + ky * 3 + kx] = vv;
            }
        }
    }

    #pragma unroll
    for (int uv = 0; uv < 4; uv++) {
        float acc[24];
        #pragma unroll
        for (int o = 0; o < 24; o++) acc[o] = sB[uv * 24 + o];

        const float4* wrow = (const float4*)(sW + uv * 648);
        #pragma unroll
        for (int t = 0; t < 27; t++) {
            float xv = patch[t];
            #pragma unroll
            for (int q = 0; q < 6; q++) {
                float4 wv = wrow[t * 6 + q];
                acc[q * 4 + 0] = fmaf(wv.x, xv, acc[q * 4 + 0]);
                acc[q * 4 + 1] = fmaf(wv.y, xv, acc[q * 4 + 1]);
                acc[q * 4 + 2] = fmaf(wv.z, xv, acc[q * 4 + 2]);
                acc[q * 4 + 3] = fmaf(wv.w, xv, acc[q * 4 + 3]);
            }
        }

        float lg0 = acc[5], lg1 = acc[11], lg2 = acc[17], lg3 = acc[23];
        float m = fmaxf(fmaxf(lg0, lg1), fmaxf(lg2, lg3));
        float w0 = __expf(lg0 - m), w1 = __expf(lg1 - m);
        float w2 = __expf(lg2 - m), w3 = __expf(lg3 - m);
        float inv = 1.f / (w0 + w1 + w2 + w3);

        float r = 0.f, g = 0.f, bl = 0.f, ox = 0.f, oy = 0.f;
        #pragma unroll
        for (int k = 0; k < 4; k++) {
            float wk = ((k == 0) ? w0 : (k == 1) ? w1 : (k == 2) ? w2 : w3) * inv;
            r  = fmaf(acc[k * 6 + 0], wk, r);
            g  = fmaf(acc[k * 6 + 1], wk, g);
            bl = fmaf(acc[k * 6 + 2], wk, bl);
            ox = fmaf(tanh_approx(acc[k * 6 + 3]), wk, ox);
            oy = fmaf(tanh_approx(acc[k * 6 + 4]), wk, oy);
        }

        int u = uv >> 1, v = uv & 1;
        int gy = 2 * i + u, gx = 2 * j + v;
        float cx = (float)gx + 2.f * ox - 1.f;
        float cy = (float)gy + 2.f * oy - 1.f;

        int gidx = b * NGAUSS + gy * GW + gx;
        g_center[gidx] = make_float2(cx, cy);
        g_color[gidx]  = make_float4(r, g, bl, 0.f);
    }
}

// ---------------------------------------------------------------------------
// Kernel 2: rasterize. One CTA per 16x16 tile per batch (1024 CTAs).
// Effective footprint 4x4 (alpha cutoff kills |d|>=2); gather halo 22x22;
// stride-5 lane permutation spreads footprints.
// CHANGE vs R4: accumulator layout acc[3*p + ch] instead of [ch][p].
// The old plane stride (256 words = 0 mod 32 banks) made each splat's three
// channel atomics a guaranteed 3-way same-bank conflict; interleaving puts
// them in 3 consecutive banks. Final-store reads at stride 3 (coprime to
// 32) stay conflict-free and the global stores stay coalesced.
// ---------------------------------------------------------------------------
__global__ void __launch_bounds__(256) raster_kernel(float* __restrict__ out)
{
    __shared__ float acc[3 * TH * TW];  // interleaved [p][ch]

    int tx0 = (blockIdx.x & 15) * TW;
    int ty0 = (blockIdx.x >> 4) * TH;
    int b   = blockIdx.y;

    for (int p = threadIdx.x; p < 3 * TH * TW; p += 256) acc[p] = 0.f;
    __syncthreads();

    const float2* ctr = g_center + b * NGAUSS;
    const float4* col = g_color  + b * NGAUSS;

    for (int idx = threadIdx.x; idx < RSX * RSY; idx += 256) {
        int ry = idx / RSX;
        int j  = idx - ry * RSX;
        int rx = (j * 5) % RSX;
        int gy = ty0 - 2 + ry;
        int gx = tx0 - 2 + rx;
        if ((unsigned)gy >= GH || (unsigned)gx >= GW) continue;

        int gi = gy * GW + gx;
        float2 c = ctr[gi];

        float ixf = floorf(c.x);
        float iyf = floorf(c.y);

        int txl = (int)ixf - 1 - tx0;
        int tyl = (int)iyf - 1 - ty0;
        if (txl >= TW || txl <= -4 || tyl >= TH || tyl <= -4) continue;

        float4 rgbv = col[gi];

        float ex[4], ey[4];
        #pragma unroll
        for (int o = 0; o < 4; o++) {
            float dx = ixf + (float)(o - 1) - c.x;
            float dy = iyf + (float)(o - 1) - c.y;
            ex[o] = __expf(-2.f * dx * dx);
            ey[o] = __expf(-2.f * dy * dy);
        }

        #pragma unroll
        for (int oy = 0; oy < 4; oy++) {
            int ty = tyl + oy;
            if ((unsigned)ty >= TH) continue;
            float eyv = ey[oy];
            #pragma unroll
            for (int ox = 0; ox < 4; ox++) {
                int tx = txl + ox;
                if ((unsigned)tx >= TW) continue;
                float a = fminf(eyv * ex[ox], 0.999f);
                if (a > (1.0f / 255.0f)) {
                    int p3 = (ty * TW + tx) * 3;
                    atomicAdd(&acc[p3 + 0], a * rgbv.x);
                    atomicAdd(&acc[p3 + 1], a * rgbv.y);
                    atomicAdd(&acc[p3 + 2], a * rgbv.z);
                }
            }
        }
    }
    __syncthreads();

    float* ob = out + (size_t)b * 3 * IMH * IMW;
    for (int p = threadIdx.x; p < TH * TW; p += 256) {
        int ty = p >> 4;
        int tx = p & 15;
        int o  = (ty0 + ty) * IMW + (tx0 + tx);
        #pragma unroll
        for (int ch = 0; ch < 3; ch++) {
            float vv = acc[p * 3 + ch];
            ob[ch * IMH * IMW + o] = fminf(fmaxf(vv, 0.f), 1.f);
        }
    }
}

// ---------------------------------------------------------------------------
// Launch: fold -> predict -> raster, all graph-capturable, no allocs/syncs.
// Inputs (metadata order): inp, w_enc, b_enc, w_head, b_head, scale(unused)
// ---------------------------------------------------------------------------
extern "C" void kernel_launch(void* const* d_in, const int* in_sizes, int n_in,
                              void* d_out, int out_size)
{
    const float* inp    = (const float*)d_in[0];
    const float* w_enc  = (const float*)d_in[1];
    const float* b_enc  = (const float*)d_in[2];
    const float* w_head = (const float*)d_in[3];
    const float* b_head = (const float*)d_in[4];
    float* out = (float*)d_out;

    fold_kernel<<<96, 128>>>(w_enc, b_enc, w_head, b_head);
    predict_kernel<<<1024, 64>>>(inp);

    dim3 g(256, BATCH);
    raster_kernel<<<g, 256>>>(out);
}

// round 9
// speedup vs baseline: 1.0864x; 1.0779x over previous
#include <cuda_runtime.h>
#include <math.h>

// ---------------------------------------------------------------------------
// GRAPEIso: conv3x3(3->1024) + pixel_shuffle(4) + pixel_unshuffle(2) + head
// algebraically folded into a 96-output 3x3 conv, then Gaussian splatting
// with exclusive shared-memory image tiles (no global atomics).
// Fixed shapes: B=4, inp 3x128x128, scale=2, grid 256x256 gaussians/batch,
// image 4x3x256x256 fp32 output.
// ---------------------------------------------------------------------------

#define BATCH   4
#define INH     128
#define INW     128
#define GH      256
#define GW      256
#define IMH     256
#define IMW     256
#define NGAUSS  (GH * GW)

// Raster tiling: 16x16 image tile per CTA -> 1024 CTAs. 4x4 footprint,
// 22x22 gather halo.
#define TW      16
#define TH      16
#define RSX     22
#define RSY     22

__device__ __forceinline__ float tanh_approx(float x) {
    float r;
    asm("tanh.approx.f32 %0, %1;" : "=f"(r) : "f"(x));
    return r;
}

// Scratch (allocation-free contract: __device__ globals)
__device__ float  g_weff[4 * 27 * 24];          // [uv][t][o], o contiguous
__device__ float  g_beff[4 * 24];               // [uv][o]
__device__ float2 g_center[BATCH * NGAUSS];     // (cx, cy)
__device__ float4 g_color [BATCH * NGAUSS];     // (r, g, b, pad)

// ---------------------------------------------------------------------------
// Kernel 0: weight fold v9. CTA = (uv, o): 96 CTAs x 512 threads (16 warps).
// LANE = t (0..26; lane 27 = bias), so each warp-LDG of w_enc reads one
// 27-float contiguous row (1-2 lines -> ~6 MB total L2 traffic, the R8
// lesson), while 16 warps x 16-channel fully-unrolled loops give MLP=16
// and one fat CTA per SM (the R8 regression was 128-thr CTAs at occ 5.9%
// serializing 64 latency waves). One 16x28 smem combine at the end.
// ---------------------------------------------------------------------------
__global__ void __launch_bounds__(512) fold_kernel(
    const float* __restrict__ w_enc,   // (1024, 3, 3, 3) -> [C*27 + t]
    const float* __restrict__ b_enc,   // (1024,)
    const float* __restrict__ w_head,  // (24, 256)
    const float* __restrict__ b_head)  // (24,)
{
    __shared__ float red[16][28];

    int uv = blockIdx.x / 24;          // grid 96
    int o  = blockIdx.x - uv * 24;
    int u = uv >> 1, v = uv & 1;

    int warp = threadIdx.x >> 5;
    int lane = threadIdx.x & 31;

    if (lane < 28) {
        float acc = 0.f;
        #pragma unroll
        for (int i = 0; i < 16; i++) {
            int ch = warp * 16 + i;
            int c = ch >> 2, a = (ch >> 1) & 1, e = ch & 1;
            int C = c * 16 + (2 * u + a) * 4 + (2 * v + e);
            float wh = __ldg(w_head + o * 256 + ch);           // warp-uniform
            float x  = (lane < 27) ? __ldg(w_enc + C * 27 + lane)
                                   : __ldg(b_enc + C);
            acc = fmaf(wh, x, acc);
        }
        red[warp][lane] = acc;
    }
    __syncthreads();

    if (threadIdx.x < 28) {
        int t = threadIdx.x;
        float s = 0.f;
        #pragma unroll
        for (int w = 0; w < 16; w++) s += red[w][t];
        if (t < 27) g_weff[uv * 648 + t * 24 + o] = s;
        else        g_beff[uv * 24 + o] = s + b_head[o];
    }
}

// ---------------------------------------------------------------------------
// Kernel 1: predict (frozen: R4 config + tanh.approx).
// 1024 CTAs x 64 threads; scalar FFMA; per-thread patch from global.
// ---------------------------------------------------------------------------
__global__ void __launch_bounds__(64) predict_kernel(const float* __restrict__ inp)
{
    __shared__ __align__(16) float sW[4 * 648];      // [uv][t][o]
    __shared__ float sB[4 * 24];

    for (int i = threadIdx.x; i < 4 * 648; i += 64) sW[i] = g_weff[i];
    for (int i = threadIdx.x; i < 96; i += 64) sB[i] = g_beff[i];
    __syncthreads();

    int idx = blockIdx.x * 64 + threadIdx.x;    // 0..65535
    int b   = idx >> 14;
    int rem = idx & 16383;
    int i   = rem >> 7;
    int j   = rem & 127;

    // Load 3x3x3 input patch with zero padding (SAME conv)
    float patch[27];
    const float* ib = inp + (size_t)b * 3 * INH * INW;
    #pragma unroll
    for (int ic = 0; ic < 3; ic++) {
        #pragma unroll
        for (int ky = 0; ky < 3; ky++) {
            int y = i + ky - 1;
            #pragma unroll
            for (int kx = 0; kx < 3; kx++) {
                int x = j + kx - 1;
                float vv = 0.f;
                if ((unsigned)y < INH && (unsigned)x < INW)
                    vv = __ldg(ib + ic * INH * INW + y * INW + x);
                patch[ic * 9 + ky * 3 + kx] = vv;
            }
        }
    }

    #pragma unroll
    for (int uv = 0; uv < 4; uv++) {
        float acc[24];
        #pragma unroll
        for (int o = 0; o < 24; o++) acc[o] = sB[uv * 24 + o];

        const float4* wrow = (const float4*)(sW + uv * 648);
        #pragma unroll
        for (int t = 0; t < 27; t++) {
            float xv = patch[t];
            #pragma unroll
            for (int q = 0; q < 6; q++) {
                float4 wv = wrow[t * 6 + q];
                acc[q * 4 + 0] = fmaf(wv.x, xv, acc[q * 4 + 0]);
                acc[q * 4 + 1] = fmaf(wv.y, xv, acc[q * 4 + 1]);
                acc[q * 4 + 2] = fmaf(wv.z, xv, acc[q * 4 + 2]);
                acc[q * 4 + 3] = fmaf(wv.w, xv, acc[q * 4 + 3]);
            }
        }

        float lg0 = acc[5], lg1 = acc[11], lg2 = acc[17], lg3 = acc[23];
        float m = fmaxf(fmaxf(lg0, lg1), fmaxf(lg2, lg3));
        float w0 = __expf(lg0 - m), w1 = __expf(lg1 - m);
        float w2 = __expf(lg2 - m), w3 = __expf(lg3 - m);
        float inv = 1.f / (w0 + w1 + w2 + w3);

        float r = 0.f, g = 0.f, bl = 0.f, ox = 0.f, oy = 0.f;
        #pragma unroll
        for (int k = 0; k < 4; k++) {
            float wk = ((k == 0) ? w0 : (k == 1) ? w1 : (k == 2) ? w2 : w3) * inv;
            r  = fmaf(acc[k * 6 + 0], wk, r);
            g  = fmaf(acc[k * 6 + 1], wk, g);
            bl = fmaf(acc[k * 6 + 2], wk, bl);
            ox = fmaf(tanh_approx(acc[k * 6 + 3]), wk, ox);
            oy = fmaf(tanh_approx(acc[k * 6 + 4]), wk, oy);
        }

        int u = uv >> 1, v = uv & 1;
        int gy = 2 * i + u, gx = 2 * j + v;
        float cx = (float)gx + 2.f * ox - 1.f;
        float cy = (float)gy + 2.f * oy - 1.f;

        int gidx = b * NGAUSS + gy * GW + gx;
        g_center[gidx] = make_float2(cx, cy);
        g_color[gidx]  = make_float4(r, g, bl, 0.f);
    }
}

// ---------------------------------------------------------------------------
// Kernel 2: rasterize (frozen: R8 version - interleaved acc[3p+ch] measured
// ~3us better than plane layout). One CTA per 16x16 tile per batch.
// Effective footprint 4x4; gather halo 22x22; stride-5 lane permutation.
// ---------------------------------------------------------------------------
__global__ void __launch_bounds__(256) raster_kernel(float* __restrict__ out)
{
    __shared__ float acc[3 * TH * TW];  // interleaved [p][ch]

    int tx0 = (blockIdx.x & 15) * TW;
    int ty0 = (blockIdx.x >> 4) * TH;
    int b   = blockIdx.y;

    for (int p = threadIdx.x; p < 3 * TH * TW; p += 256) acc[p] = 0.f;
    __syncthreads();

    const float2* ctr = g_center + b * NGAUSS;
    const float4* col = g_color  + b * NGAUSS;

    for (int idx = threadIdx.x; idx < RSX * RSY; idx += 256) {
        int ry = idx / RSX;
        int j  = idx - ry * RSX;
        int rx = (j * 5) % RSX;
        int gy = ty0 - 2 + ry;
        int gx = tx0 - 2 + rx;
        if ((unsigned)gy >= GH || (unsigned)gx >= GW) continue;

        int gi = gy * GW + gx;
        float2 c = ctr[gi];

        float ixf = floorf(c.x);
        float iyf = floorf(c.y);

        int txl = (int)ixf - 1 - tx0;
        int tyl = (int)iyf - 1 - ty0;
        if (txl >= TW || txl <= -4 || tyl >= TH || tyl <= -4) continue;

        float4 rgbv = col[gi];

        float ex[4], ey[4];
        #pragma unroll
        for (int o = 0; o < 4; o++) {
            float dx = ixf + (float)(o - 1) - c.x;
            float dy = iyf + (float)(o - 1) - c.y;
            ex[o] = __expf(-2.f * dx * dx);
            ey[o] = __expf(-2.f * dy * dy);
        }

        #pragma unroll
        for (int oy = 0; oy < 4; oy++) {
            int ty = tyl + oy;
            if ((unsigned)ty >= TH) continue;
            float eyv = ey[oy];
            #pragma unroll
            for (int ox = 0; ox < 4; ox++) {
                int tx = txl + ox;
                if ((unsigned)tx >= TW) continue;
                float a = fminf(eyv * ex[ox], 0.999f);
                if (a > (1.0f / 255.0f)) {
                    int p3 = (ty * TW + tx) * 3;
                    atomicAdd(&acc[p3 + 0], a * rgbv.x);
                    atomicAdd(&acc[p3 + 1], a * rgbv.y);
                    atomicAdd(&acc[p3 + 2], a * rgbv.z);
                }
            }
        }
    }
    __syncthreads();

    float* ob = out + (size_t)b * 3 * IMH * IMW;
    for (int p = threadIdx.x; p < TH * TW; p += 256) {
        int ty = p >> 4;
        int tx = p & 15;
        int o  = (ty0 + ty) * IMW + (tx0 + tx);
        #pragma unroll
        for (int ch = 0; ch < 3; ch++) {
            float vv = acc[p * 3 + ch];
            ob[ch * IMH * IMW + o] = fminf(fmaxf(vv, 0.f), 1.f);
        }
    }
}

// ---------------------------------------------------------------------------
// Launch: fold -> predict -> raster, all graph-capturable, no allocs/syncs.
// Inputs (metadata order): inp, w_enc, b_enc, w_head, b_head, scale(unused)
// ---------------------------------------------------------------------------
extern "C" void kernel_launch(void* const* d_in, const int* in_sizes, int n_in,
                              void* d_out, int out_size)
{
    const float* inp    = (const float*)d_in[0];
    const float* w_enc  = (const float*)d_in[1];
    const float* b_enc  = (const float*)d_in[2];
    const float* w_head = (const float*)d_in[3];
    const float* b_head = (const float*)d_in[4];
    float* out = (float*)d_out;

    fold_kernel<<<96, 512>>>(w_enc, b_enc, w_head, b_head);
    predict_kernel<<<1024, 64>>>(inp);

    dim3 g(256, BATCH);
    raster_kernel<<<g, 256>>>(out);
}